// round 5
// baseline (speedup 1.0000x reference)
#include <cuda_runtime.h>
#include <math.h>

#define BSZ   16
#define NSEQ  1024
#define CDIM  768
#define NH2   24
#define HD    64
#define W2D   1536
#define KMB   16
#define NMB   64

// ---------------- scratch (static device globals; no allocation) -------------
__device__ float g_qkv[BSZ * NSEQ * 3 * CDIM];   // [B,N,2304]  q|k|v
__device__ float g_lr [BSZ * NSEQ * NH2];        // [B,N,24]
__device__ float g_Z  [BSZ * NSEQ * W2D];        // [B,N,1536]
__device__ float g_U  [BSZ * NSEQ * CDIM];       // [B,N,768]

__device__ __forceinline__ float warpSum(float v) {
    #pragma unroll
    for (int o = 16; o; o >>= 1) v += __shfl_xor_sync(0xffffffffu, v, o);
    return v;
}

// ---------------- generic fp32 SGEMM: C[M,N] = A[M,K]@B[K,N] (+bias) ---------
// Requires M%128==0, N%128==0, K%8==0. 256 threads, 128x128 tile, 8x8 micro.
__global__ __launch_bounds__(256) void sgemm_kernel(
    int M, int N, int Kd,
    const float* __restrict__ A, const float* __restrict__ B,
    const float* __restrict__ bias, float* __restrict__ C)
{
    __shared__ float As[8][128];
    __shared__ float Bs[8][128];
    const int tid  = threadIdx.x;
    const int brow = blockIdx.y * 128;
    const int bcol = blockIdx.x * 128;
    const int trow = (tid >> 4) * 8;
    const int tcol = (tid & 15) * 8;

    float acc[8][8];
    #pragma unroll
    for (int i = 0; i < 8; i++)
        #pragma unroll
        for (int j = 0; j < 8; j++) acc[i][j] = 0.f;

    const int arow = tid >> 1, acol = (tid & 1) * 4;
    const int brl  = tid >> 5, bcl  = (tid & 31) * 4;
    const float* Ap = A + (long)(brow + arow) * Kd + acol;
    const float* Bp = B + (long)brl * N + bcol + bcl;

    for (int k0 = 0; k0 < Kd; k0 += 8) {
        float4 av = *(const float4*)Ap;
        float4 bv = *(const float4*)Bp;
        As[acol + 0][arow] = av.x;
        As[acol + 1][arow] = av.y;
        As[acol + 2][arow] = av.z;
        As[acol + 3][arow] = av.w;
        *(float4*)&Bs[brl][bcl] = bv;
        __syncthreads();
        #pragma unroll
        for (int kk = 0; kk < 8; kk++) {
            float4 a0 = *(const float4*)&As[kk][trow];
            float4 a1 = *(const float4*)&As[kk][trow + 4];
            float4 b0 = *(const float4*)&Bs[kk][tcol];
            float4 b1 = *(const float4*)&Bs[kk][tcol + 4];
            float ar[8] = {a0.x, a0.y, a0.z, a0.w, a1.x, a1.y, a1.z, a1.w};
            float br[8] = {b0.x, b0.y, b0.z, b0.w, b1.x, b1.y, b1.z, b1.w};
            #pragma unroll
            for (int i = 0; i < 8; i++)
                #pragma unroll
                for (int j = 0; j < 8; j++) acc[i][j] += ar[i] * br[j];
        }
        __syncthreads();
        Ap += 8;
        Bp += (long)8 * N;
    }
    #pragma unroll
    for (int i = 0; i < 8; i++) {
        float* crow = C + (long)(brow + trow + i) * N + bcol + tcol;
        #pragma unroll
        for (int j = 0; j < 8; j++) {
            float v = acc[i][j];
            if (bias) v += bias[bcol + tcol + j];
            crow[j] = v;
        }
    }
}

// ---------------- lr gate: lr[b,n,h] = sigmoid(xx . lr_w[:,h] + lr_b[h])/64 --
// xx[b,n,:] = [x[b,n,:], x[b,N-1-n,:]]. 256 threads, one (b,n) row per block.
__global__ __launch_bounds__(256) void lr_kernel(
    const float* __restrict__ x, const float* __restrict__ lr_w,
    const float* __restrict__ lr_b, float* __restrict__ lrout)
{
    const int bn = blockIdx.x;
    const int b = bn >> 10, n = bn & 1023;
    __shared__ float row[W2D];
    __shared__ float red[8][24];
    const int tid = threadIdx.x;
    const float* xf = x + (long)bn * CDIM;
    const float* xb = x + ((long)(b << 10) + (1023 - n)) * CDIM;
    for (int c = tid; c < CDIM; c += 256) {
        row[c] = xf[c];
        row[CDIM + c] = xb[c];
    }
    __syncthreads();

    float acc[24];
    #pragma unroll
    for (int h = 0; h < 24; h++) acc[h] = 0.f;
    #pragma unroll
    for (int i = 0; i < 6; i++) {
        int c = tid + i * 256;
        float xv = row[c];
        const float4* wp = (const float4*)(lr_w + c * 24);
        #pragma unroll
        for (int q = 0; q < 6; q++) {
            float4 w4 = wp[q];
            acc[q * 4 + 0] += xv * w4.x;
            acc[q * 4 + 1] += xv * w4.y;
            acc[q * 4 + 2] += xv * w4.z;
            acc[q * 4 + 3] += xv * w4.w;
        }
    }
    const int lane = tid & 31, wid = tid >> 5;
    #pragma unroll
    for (int h = 0; h < 24; h++) {
        float s = warpSum(acc[h]);
        if (lane == 0) red[wid][h] = s;
    }
    __syncthreads();
    if (tid < 24) {
        float s = 0.f;
        #pragma unroll
        for (int w = 0; w < 8; w++) s += red[w][tid];
        float v = 1.f / (1.f + expf(-(s + lr_b[tid])));
        lrout[(long)bn * 24 + tid] = v * (1.f / 64.f);
    }
}

// ---------------- TTT scan: one (h,b) chain per CTA, 512 threads -------------
__global__ __launch_bounds__(512) void ttt_kernel(
    const float* __restrict__ qkv, const float* __restrict__ lrbuf,
    const float* __restrict__ W1,  const float* __restrict__ b1,
    const float* __restrict__ lnw, const float* __restrict__ lnb,
    const float* __restrict__ tdelta, float* __restrict__ Zout)
{
    const int h = blockIdx.x;   // 0..23
    const int b = blockIdx.y;   // 0..15
    __shared__ float Ws[HD][HD];
    __shared__ float xq_s[KMB][HD], xk_s[KMB][HD], grad_s[KMB][HD];
    __shared__ float lrm_s[KMB];
    const int tid = threadIdx.x, wi = tid >> 5, lane = tid & 31;

    for (int i = tid; i < HD * HD; i += 512)
        Ws[i >> 6][i & 63] = W1[h * HD * HD + i];

    const int d0 = 2 * lane, d1 = 2 * lane + 1;
    float breg0 = b1[h * HD + d0], breg1 = b1[h * HD + d1];
    const float g0  = lnw[h * HD + d0], g1  = lnw[h * HD + d1];
    const float bt0 = lnb[h * HD + d0], bt1 = lnb[h * HD + d1];
    const float tok_i    = fmaxf(1.f / (float)(wi + 1) + tdelta[wi], 0.f);
    const float tok_last = fmaxf(1.f / 16.f + tdelta[15], 0.f);
    const float inv = powf(10000.f, -(float)lane / 32.f);
    float sv, cv;
    sincosf((float)wi * inv, &sv, &cv);  // pos = n % 16 = wi
    const bool  flipd   = (h >= 12);
    const int   srcCol  = (flipd ? (h - 12) : h) * HD;

    for (int m = 0; m < NMB; m++) {
        // ---- phase A: gather tokens (head map + flip), apply rotary --------
        const int n  = m * KMB + wi;
        const int sn = flipd ? (NSEQ - 1 - n) : n;
        const float* base = qkv + (long)(b * NSEQ + sn) * (3 * CDIM) + srcCol;
        float q0 = base[d0],            q1 = base[d1];
        float k0 = base[CDIM + d0],     k1 = base[CDIM + d1];
        float v0 = base[2 * CDIM + d0], v1 = base[2 * CDIM + d1];
        const float qr0 = q0 * cv - q1 * sv, qr1 = q0 * sv + q1 * cv;
        const float kr0 = k0 * cv - k1 * sv, kr1 = k0 * sv + k1 * cv;
        xq_s[wi][d0] = qr0; xq_s[wi][d1] = qr1;
        xk_s[wi][d0] = kr0; xk_s[wi][d1] = kr1;
        if (wi == 0 && lane < KMB)
            lrm_s[lane] = lrbuf[(long)(b * NSEQ + m * KMB + lane) * NH2 + h];
        __syncthreads();

        // ---- phase B: Z1 = xk@W + b, xqW = xq@W, grad = ln_l2_bwd ----------
        float z0 = breg0, z1 = breg1, a0 = 0.f, a1 = 0.f;
        #pragma unroll 16
        for (int e = 0; e < HD; e++) {
            const float ke = xk_s[wi][e], qe = xq_s[wi][e];
            const float2 wv = *(const float2*)&Ws[e][d0];
            z0 += ke * wv.x; z1 += ke * wv.y;
            a0 += qe * wv.x; a1 += qe * wv.y;
        }
        const float mu = warpSum(z0 + z1) * (1.f / 64.f);
        const float zc0 = z0 - mu, zc1 = z1 - mu;
        const float var = warpSum(zc0 * zc0 + zc1 * zc1) * (1.f / 64.f);
        const float rstd = rsqrtf(var + 1e-6f);
        const float xh0 = zc0 * rstd, xh1 = zc1 * rstd;
        const float t0 = v0 - kr0, t1 = v1 - kr1;
        const float go0 = g0 * xh0 + bt0 - t0, go1 = g1 * xh1 + bt1 - t1;
        const float gx0 = go0 * g0, gx1 = go1 * g1;
        const float s1 = warpSum(gx0 + gx1);
        const float s2 = warpSum(gx0 * xh0 + gx1 * xh1);
        const float cdn = rstd * (1.f / 64.f);
        const float gr0 = (64.f * gx0 - s1 - xh0 * s2) * cdn;
        const float gr1 = (64.f * gx1 - s1 - xh1 * s2) * cdn;
        grad_s[wi][d0] = gr0; grad_s[wi][d1] = gr1;
        __syncthreads();

        // ---- phase C: attn, Z1_bar, output LN; then W/b rank-16 update -----
        float acc0 = a0 + breg0, acc1 = a1 + breg1;
        for (int j = 0; j <= wi; j++) {
            const float2 kk2 = *(const float2*)&xk_s[j][d0];
            float p = warpSum(qr0 * kk2.x + qr1 * kk2.y);     // attn[i][j]
            const float coef = tok_i * lrm_s[j] * (1.f + p);  // eta*(mask+attn)
            const float2 gg2 = *(const float2*)&grad_s[j][d0];
            acc0 -= coef * gg2.x;
            acc1 -= coef * gg2.y;
        }
        const float mu2 = warpSum(acc0 + acc1) * (1.f / 64.f);
        const float c0 = acc0 - mu2, c1 = acc1 - mu2;
        const float var2 = warpSum(c0 * c0 + c1 * c1) * (1.f / 64.f);
        const float rs2 = rsqrtf(var2 + 1e-6f);
        float2 ov = make_float2(qr0 + g0 * c0 * rs2 + bt0,
                                qr1 + g1 * c1 * rs2 + bt1);
        *(float2*)&Zout[(long)(b * NSEQ + n) * W2D + h * HD + d0] = ov;

        // b update (register-replicated, redundant per warp)
        float db0 = 0.f, db1 = 0.f;
        #pragma unroll
        for (int k = 0; k < KMB; k++) {
            const float c = lrm_s[k];
            const float2 gg2 = *(const float2*)&grad_s[k][d0];
            db0 += c * gg2.x; db1 += c * gg2.y;
        }
        breg0 -= tok_last * db0;
        breg1 -= tok_last * db1;

        // W update: each thread owns an exclusive 8-float slice of W
        {
            const int e  = tid >> 3;
            const int dd = (tid & 7) * 8;
            float wacc[8];
            #pragma unroll
            for (int d = 0; d < 8; d++) wacc[d] = Ws[e][dd + d];
            #pragma unroll
            for (int k = 0; k < KMB; k++) {
                const float c = tok_last * lrm_s[k] * xk_s[k][e];
                const float4 ga = *(const float4*)&grad_s[k][dd];
                const float4 gb = *(const float4*)&grad_s[k][dd + 4];
                wacc[0] -= c * ga.x; wacc[1] -= c * ga.y;
                wacc[2] -= c * ga.z; wacc[3] -= c * ga.w;
                wacc[4] -= c * gb.x; wacc[5] -= c * gb.y;
                wacc[6] -= c * gb.z; wacc[7] -= c * gb.w;
            }
            #pragma unroll
            for (int d = 0; d < 8; d++) Ws[e][dd + d] = wacc[d];
        }
        __syncthreads();
    }
}

// ---------------- post layernorm over W2=1536, in place ----------------------
__global__ __launch_bounds__(256) void postln_kernel(
    float* __restrict__ Z, const float* __restrict__ w, const float* __restrict__ bb)
{
    float* z = Z + (long)blockIdx.x * W2D;
    __shared__ float red[8];
    const int tid = threadIdx.x, lane = tid & 31, wid = tid >> 5;
    float local[6];
    float s = 0.f;
    #pragma unroll
    for (int i = 0; i < 6; i++) { local[i] = z[tid + i * 256]; s += local[i]; }
    s = warpSum(s);
    if (lane == 0) red[wid] = s;
    __syncthreads();
    float tot = 0.f;
    #pragma unroll
    for (int i = 0; i < 8; i++) tot += red[i];
    const float mu = tot * (1.f / 1536.f);
    __syncthreads();
    float v = 0.f;
    #pragma unroll
    for (int i = 0; i < 6; i++) { float d = local[i] - mu; v += d * d; }
    v = warpSum(v);
    if (lane == 0) red[wid] = v;
    __syncthreads();
    float tv = 0.f;
    #pragma unroll
    for (int i = 0; i < 8; i++) tv += red[i];
    const float rstd = rsqrtf(tv * (1.f / 1536.f) + 1e-6f);
    #pragma unroll
    for (int i = 0; i < 6; i++) {
        int c = tid + i * 256;
        z[c] = (local[i] - mu) * rstd * w[c] + bb[c];
    }
}

// ---------------- GLU with sequence flip: u = zf[n] * zb[N-1-n] --------------
__global__ __launch_bounds__(256) void glu_kernel(
    const float* __restrict__ Z, float* __restrict__ U)
{
    const long idx = (long)blockIdx.x * 256 + threadIdx.x;  // B*N*768
    const int c = (int)(idx % CDIM);
    const long bn = idx / CDIM;
    const int n = (int)(bn & 1023);
    const long b = bn >> 10;
    const float zf = Z[((b << 10) + n) * W2D + c];
    const float zb = Z[((b << 10) + (1023 - n)) * W2D + CDIM + c];
    U[idx] = zf * zb;
}

// ---------------- launch -----------------------------------------------------
extern "C" void kernel_launch(void* const* d_in, const int* in_sizes, int n_in,
                              void* d_out, int out_size)
{
    const float* x      = (const float*)d_in[0];
    const float* qkv_w  = (const float*)d_in[1];
    const float* proj_w = (const float*)d_in[2];
    const float* proj_b = (const float*)d_in[3];
    const float* W1     = (const float*)d_in[4];
    const float* b1     = (const float*)d_in[5];
    const float* ttt_w  = (const float*)d_in[6];
    const float* ttt_b  = (const float*)d_in[7];
    const float* pln_w  = (const float*)d_in[8];
    const float* pln_b  = (const float*)d_in[9];
    const float* lr_w   = (const float*)d_in[10];
    const float* lr_b   = (const float*)d_in[11];
    const float* tdelta = (const float*)d_in[12];
    float* out = (float*)d_out;

    float *p_qkv, *p_lr, *p_Z, *p_U;
    cudaGetSymbolAddress((void**)&p_qkv, g_qkv);
    cudaGetSymbolAddress((void**)&p_lr,  g_lr);
    cudaGetSymbolAddress((void**)&p_Z,   g_Z);
    cudaGetSymbolAddress((void**)&p_U,   g_U);

    const int M = BSZ * NSEQ;  // 16384

    // 1) qkv = x @ qkv_w                [16384,768] x [768,2304]
    sgemm_kernel<<<dim3((3 * CDIM) / 128, M / 128), 256>>>(
        M, 3 * CDIM, CDIM, x, qkv_w, nullptr, p_qkv);
    // 2) lr gates
    lr_kernel<<<M, 256>>>(x, lr_w, lr_b, p_lr);
    // 3) TTT scan -> Z [B,N,1536]
    ttt_kernel<<<dim3(NH2, BSZ), 512>>>(p_qkv, p_lr, W1, b1, ttt_w, ttt_b,
                                        tdelta, p_Z);
    // 4) post layernorm (in place)
    postln_kernel<<<M, 256>>>(p_Z, pln_w, pln_b);
    // 5) gated flip multiply -> U [B,N,768]
    glu_kernel<<<(M * CDIM) / 256, 256>>>(p_Z, p_U);
    // 6) out = U @ proj_w + proj_b     [16384,768] x [768,768]
    sgemm_kernel<<<dim3(CDIM / 128, M / 128), 256>>>(
        M, CDIM, CDIM, p_U, proj_w, proj_b, out);
}

// round 9
// speedup vs baseline: 1.1232x; 1.1232x over previous
#include <cuda_runtime.h>
#include <stdint.h>
#include <math.h>

#define BSZ   16
#define NSEQ  1024
#define CDIM  768
#define NH2   24
#define HD    64
#define W2D   1536
#define KMB   16
#define NMB   64

// ---------------- scratch (static device globals; no allocation) -------------
__device__ float g_qkv[BSZ * NSEQ * 3 * CDIM];   // [B,N,2304]  q|k|v
__device__ float g_lr [BSZ * NSEQ * NH2];        // [B,N,24]
__device__ float g_Z  [BSZ * NSEQ * W2D];        // [B,N,1536]
__device__ float g_U  [BSZ * NSEQ * CDIM];       // [B,N,768]

__device__ __forceinline__ float warpSum(float v) {
    #pragma unroll
    for (int o = 16; o; o >>= 1) v += __shfl_xor_sync(0xffffffffu, v, o);
    return v;
}

// ================= 3xTF32 tensor-core GEMM (fp32 accuracy) ===================
// C[M,N] = A[M,K] @ B[K,N] (+bias). M%128==0, N%128==0, K%32==0.
// 256 threads. Block tile 128x128x32, warp tile 64x32, mma.m16n8k8.tf32.
// Each operand split hi/lo (round-to-nearest tf32); D += Al*Bh + Ah*Bl + Ah*Bh.

#define ALD 36
#define BLD 136
#define ASZ (128 * ALD)
#define BSZ_T (32 * BLD)
#define SMEM_BYTES (2 * (ASZ + BSZ_T) * 4)

__device__ __forceinline__ void cp16(float* s, const float* g) {
    unsigned int sa = (unsigned int)__cvta_generic_to_shared(s);
    asm volatile("cp.async.cg.shared.global [%0], [%1], 16;\n" :: "r"(sa), "l"(g));
}
__device__ __forceinline__ void cp_commit() {
    asm volatile("cp.async.commit_group;\n");
}
__device__ __forceinline__ void cp_wait0() {
    asm volatile("cp.async.wait_group 0;\n");
}
__device__ __forceinline__ void mma_tf32(float* d, const unsigned int* a,
                                         const unsigned int* b) {
    asm volatile(
        "mma.sync.aligned.m16n8k8.row.col.f32.tf32.tf32.f32 "
        "{%0,%1,%2,%3}, {%4,%5,%6,%7}, {%8,%9}, {%0,%1,%2,%3};\n"
        : "+f"(d[0]), "+f"(d[1]), "+f"(d[2]), "+f"(d[3])
        : "r"(a[0]), "r"(a[1]), "r"(a[2]), "r"(a[3]), "r"(b[0]), "r"(b[1]));
}
__device__ __forceinline__ void tf32_split(float v, unsigned int& hi,
                                           unsigned int& lo) {
    asm("cvt.rna.tf32.f32 %0, %1;" : "=r"(hi) : "f"(v));
    float lv = v - __uint_as_float(hi);
    asm("cvt.rna.tf32.f32 %0, %1;" : "=r"(lo) : "f"(lv));
}

__device__ __forceinline__ void load_stage(
    float* As, float* Bs, const float* A, const float* B,
    int N, int Kd, int brow, int bcol, int k0, int tid)
{
    #pragma unroll
    for (int j = 0; j < 4; j++) {
        int ch = tid + j * 256;            // 1024 chunks of 16B for A (128x32)
        int r = ch >> 3, cc = (ch & 7) * 4;
        cp16(As + r * ALD + cc, A + (long)(brow + r) * Kd + k0 + cc);
    }
    #pragma unroll
    for (int j = 0; j < 4; j++) {
        int ch = tid + j * 256;            // 1024 chunks for B (32x128)
        int r = ch >> 5, cc = (ch & 31) * 4;
        cp16(Bs + r * BLD + cc, B + (long)(k0 + r) * N + bcol + cc);
    }
}

__global__ __launch_bounds__(256) void gemm_tf32_kernel(
    int M, int N, int Kd,
    const float* __restrict__ A, const float* __restrict__ B,
    const float* __restrict__ bias, float* __restrict__ C)
{
    extern __shared__ float smem[];
    float* Abuf[2] = { smem, smem + ASZ + BSZ_T };
    float* Bbuf[2] = { smem + ASZ, smem + ASZ + BSZ_T + ASZ };

    const int tid = threadIdx.x;
    const int brow = blockIdx.y * 128;
    const int bcol = blockIdx.x * 128;
    const int w = tid >> 5, lane = tid & 31;
    const int wr = w >> 2, wc = w & 3;          // warp grid 2 x 4
    const int g = lane >> 2, tg = lane & 3;     // mma group / thread-in-group

    float acc[4][4][4];
    #pragma unroll
    for (int i = 0; i < 4; i++)
        #pragma unroll
        for (int j = 0; j < 4; j++)
            #pragma unroll
            for (int r = 0; r < 4; r++) acc[i][j][r] = 0.f;

    const int KT = Kd / 32;
    load_stage(Abuf[0], Bbuf[0], A, B, N, Kd, brow, bcol, 0, tid);
    cp_commit();

    for (int kt = 0; kt < KT; kt++) {
        cp_wait0();
        __syncthreads();
        if (kt + 1 < KT) {
            load_stage(Abuf[(kt + 1) & 1], Bbuf[(kt + 1) & 1], A, B, N, Kd,
                       brow, bcol, (kt + 1) * 32, tid);
            cp_commit();
        }
        const float* As = Abuf[kt & 1];
        const float* Bs = Bbuf[kt & 1];

        #pragma unroll
        for (int ks = 0; ks < 4; ks++) {
            const int kk = ks * 8;
            unsigned int ah[4][4], al[4][4];
            #pragma unroll
            for (int i = 0; i < 4; i++) {
                const float* ap = As + (wr * 64 + i * 16 + g) * ALD + kk + tg;
                tf32_split(ap[0],            ah[i][0], al[i][0]);
                tf32_split(ap[8 * ALD],      ah[i][1], al[i][1]);
                tf32_split(ap[4],            ah[i][2], al[i][2]);
                tf32_split(ap[8 * ALD + 4],  ah[i][3], al[i][3]);
            }
            unsigned int bh[4][2], bl[4][2];
            #pragma unroll
            for (int j = 0; j < 4; j++) {
                const float* bp = Bs + (kk + tg) * BLD + wc * 32 + j * 8 + g;
                tf32_split(bp[0],        bh[j][0], bl[j][0]);
                tf32_split(bp[4 * BLD],  bh[j][1], bl[j][1]);
            }
            #pragma unroll
            for (int i = 0; i < 4; i++)
                #pragma unroll
                for (int j = 0; j < 4; j++) {
                    mma_tf32(acc[i][j], al[i], bh[j]);   // cross terms first
                    mma_tf32(acc[i][j], ah[i], bl[j]);
                    mma_tf32(acc[i][j], ah[i], bh[j]);   // main term
                }
        }
        __syncthreads();
    }

    #pragma unroll
    for (int i = 0; i < 4; i++) {
        #pragma unroll
        for (int j = 0; j < 4; j++) {
            const int row = brow + wr * 64 + i * 16 + g;
            const int col = bcol + wc * 32 + j * 8 + tg * 2;
            float2 v0 = make_float2(acc[i][j][0], acc[i][j][1]);
            float2 v1 = make_float2(acc[i][j][2], acc[i][j][3]);
            if (bias) {
                float2 bb = *(const float2*)(bias + col);
                v0.x += bb.x; v0.y += bb.y;
                v1.x += bb.x; v1.y += bb.y;
            }
            *(float2*)&C[(long)row * N + col] = v0;
            *(float2*)&C[(long)(row + 8) * N + col] = v1;
        }
    }
}

// ---------------- lr gate: warp-per-row, 8 rows per CTA ----------------------
// lr[b,n,h] = sigmoid([x[b,n],x[b,N-1-n]] . lr_w[:,h] + lr_b[h]) / 64
__global__ __launch_bounds__(256) void lr_kernel(
    const float* __restrict__ x, const float* __restrict__ lr_w,
    const float* __restrict__ lr_b, float* __restrict__ lrout)
{
    const int w = threadIdx.x >> 5, lane = threadIdx.x & 31;
    const long bn = (long)blockIdx.x * 8 + w;
    const int b = (int)(bn >> 10), n = (int)(bn & 1023);
    const float* xf = x + bn * CDIM;
    const float* xb = x + ((long)(b << 10) + (1023 - n)) * CDIM;

    float acc[24];
    #pragma unroll
    for (int h = 0; h < 24; h++) acc[h] = 0.f;

    #pragma unroll 4
    for (int i = 0; i < 48; i++) {
        const int c = lane + i * 32;
        const float xv = (c < CDIM) ? xf[c] : xb[c - CDIM];
        const float4* wp = (const float4*)(lr_w + c * 24);
        #pragma unroll
        for (int q = 0; q < 6; q++) {
            float4 w4 = wp[q];
            acc[q * 4 + 0] += xv * w4.x;
            acc[q * 4 + 1] += xv * w4.y;
            acc[q * 4 + 2] += xv * w4.z;
            acc[q * 4 + 3] += xv * w4.w;
        }
    }
    float res = 0.f;
    #pragma unroll
    for (int h = 0; h < 24; h++) {
        float s = warpSum(acc[h]);
        if (lane == h) res = s;
    }
    if (lane < 24) {
        float v = 1.f / (1.f + expf(-(res + lr_b[lane])));
        lrout[bn * 24 + lane] = v * (1.f / 64.f);
    }
}

// ---------------- TTT scan: one (h,b) chain per CTA, 512 threads -------------
__global__ __launch_bounds__(512) void ttt_kernel(
    const float* __restrict__ qkv, const float* __restrict__ lrbuf,
    const float* __restrict__ W1,  const float* __restrict__ b1,
    const float* __restrict__ lnw, const float* __restrict__ lnb,
    const float* __restrict__ tdelta, float* __restrict__ Zout)
{
    const int h = blockIdx.x;   // 0..23
    const int b = blockIdx.y;   // 0..15
    __shared__ float Ws[HD][HD];
    __shared__ float xq_s[KMB][HD], xk_s[KMB][HD], grad_s[KMB][HD];
    __shared__ float lrm_s[KMB];
    const int tid = threadIdx.x, wi = tid >> 5, lane = tid & 31;

    for (int i = tid; i < HD * HD; i += 512)
        Ws[i >> 6][i & 63] = W1[h * HD * HD + i];

    const int d0 = 2 * lane, d1 = 2 * lane + 1;
    float breg0 = b1[h * HD + d0], breg1 = b1[h * HD + d1];
    const float g0  = lnw[h * HD + d0], g1  = lnw[h * HD + d1];
    const float bt0 = lnb[h * HD + d0], bt1 = lnb[h * HD + d1];
    const float tok_i    = fmaxf(1.f / (float)(wi + 1) + tdelta[wi], 0.f);
    const float tok_last = fmaxf(1.f / 16.f + tdelta[15], 0.f);
    const float inv = powf(10000.f, -(float)lane / 32.f);
    float sv, cv;
    sincosf((float)wi * inv, &sv, &cv);  // pos = n % 16 = wi
    const bool  flipd   = (h >= 12);
    const int   srcCol  = (flipd ? (h - 12) : h) * HD;

    for (int m = 0; m < NMB; m++) {
        // ---- phase A: gather tokens (head map + flip), apply rotary --------
        const int n  = m * KMB + wi;
        const int sn = flipd ? (NSEQ - 1 - n) : n;
        const float* base = qkv + (long)(b * NSEQ + sn) * (3 * CDIM) + srcCol;
        float q0 = base[d0],            q1 = base[d1];
        float k0 = base[CDIM + d0],     k1 = base[CDIM + d1];
        float v0 = base[2 * CDIM + d0], v1 = base[2 * CDIM + d1];
        const float qr0 = q0 * cv - q1 * sv, qr1 = q0 * sv + q1 * cv;
        const float kr0 = k0 * cv - k1 * sv, kr1 = k0 * sv + k1 * cv;
        xq_s[wi][d0] = qr0; xq_s[wi][d1] = qr1;
        xk_s[wi][d0] = kr0; xk_s[wi][d1] = kr1;
        if (wi == 0 && lane < KMB)
            lrm_s[lane] = lrbuf[(long)(b * NSEQ + m * KMB + lane) * NH2 + h];
        __syncthreads();

        // ---- phase B: Z1 = xk@W + b, xqW = xq@W, grad = ln_l2_bwd ----------
        float z0 = breg0, z1 = breg1, a0 = 0.f, a1 = 0.f;
        #pragma unroll 16
        for (int e = 0; e < HD; e++) {
            const float ke = xk_s[wi][e], qe = xq_s[wi][e];
            const float2 wv = *(const float2*)&Ws[e][d0];
            z0 += ke * wv.x; z1 += ke * wv.y;
            a0 += qe * wv.x; a1 += qe * wv.y;
        }
        const float mu = warpSum(z0 + z1) * (1.f / 64.f);
        const float zc0 = z0 - mu, zc1 = z1 - mu;
        const float var = warpSum(zc0 * zc0 + zc1 * zc1) * (1.f / 64.f);
        const float rstd = rsqrtf(var + 1e-6f);
        const float xh0 = zc0 * rstd, xh1 = zc1 * rstd;
        const float t0 = v0 - kr0, t1 = v1 - kr1;
        const float go0 = g0 * xh0 + bt0 - t0, go1 = g1 * xh1 + bt1 - t1;
        const float gx0 = go0 * g0, gx1 = go1 * g1;
        const float s1 = warpSum(gx0 + gx1);
        const float s2 = warpSum(gx0 * xh0 + gx1 * xh1);
        const float cdn = rstd * (1.f / 64.f);
        const float gr0 = (64.f * gx0 - s1 - xh0 * s2) * cdn;
        const float gr1 = (64.f * gx1 - s1 - xh1 * s2) * cdn;
        grad_s[wi][d0] = gr0; grad_s[wi][d1] = gr1;
        __syncthreads();

        // ---- phase C: attn, Z1_bar, output LN; then W/b rank-16 update -----
        float acc0 = a0 + breg0, acc1 = a1 + breg1;
        for (int j = 0; j <= wi; j++) {
            const float2 kk2 = *(const float2*)&xk_s[j][d0];
            float p = warpSum(qr0 * kk2.x + qr1 * kk2.y);     // attn[i][j]
            const float coef = tok_i * lrm_s[j] * (1.f + p);  // eta*(mask+attn)
            const float2 gg2 = *(const float2*)&grad_s[j][d0];
            acc0 -= coef * gg2.x;
            acc1 -= coef * gg2.y;
        }
        const float mu2 = warpSum(acc0 + acc1) * (1.f / 64.f);
        const float c0 = acc0 - mu2, c1 = acc1 - mu2;
        const float var2 = warpSum(c0 * c0 + c1 * c1) * (1.f / 64.f);
        const float rs2 = rsqrtf(var2 + 1e-6f);
        float2 ov = make_float2(qr0 + g0 * c0 * rs2 + bt0,
                                qr1 + g1 * c1 * rs2 + bt1);
        *(float2*)&Zout[(long)(b * NSEQ + n) * W2D + h * HD + d0] = ov;

        // b update (register-replicated, redundant per warp)
        float db0 = 0.f, db1 = 0.f;
        #pragma unroll
        for (int k = 0; k < KMB; k++) {
            const float c = lrm_s[k];
            const float2 gg2 = *(const float2*)&grad_s[k][d0];
            db0 += c * gg2.x; db1 += c * gg2.y;
        }
        breg0 -= tok_last * db0;
        breg1 -= tok_last * db1;

        // W update: each thread owns an exclusive 8-float slice of W
        {
            const int e  = tid >> 3;
            const int dd = (tid & 7) * 8;
            float wacc[8];
            #pragma unroll
            for (int d = 0; d < 8; d++) wacc[d] = Ws[e][dd + d];
            #pragma unroll
            for (int k = 0; k < KMB; k++) {
                const float c = tok_last * lrm_s[k] * xk_s[k][e];
                const float4 ga = *(const float4*)&grad_s[k][dd];
                const float4 gb = *(const float4*)&grad_s[k][dd + 4];
                wacc[0] -= c * ga.x; wacc[1] -= c * ga.y;
                wacc[2] -= c * ga.z; wacc[3] -= c * ga.w;
                wacc[4] -= c * gb.x; wacc[5] -= c * gb.y;
                wacc[6] -= c * gb.z; wacc[7] -= c * gb.w;
            }
            #pragma unroll
            for (int d = 0; d < 8; d++) Ws[e][dd + d] = wacc[d];
        }
        __syncthreads();
    }
}

// ---------------- post layernorm over W2=1536, in place ----------------------
__global__ __launch_bounds__(256) void postln_kernel(
    float* __restrict__ Z, const float* __restrict__ w, const float* __restrict__ bb)
{
    float* z = Z + (long)blockIdx.x * W2D;
    __shared__ float red[8];
    const int tid = threadIdx.x, lane = tid & 31, wid = tid >> 5;
    float local[6];
    float s = 0.f;
    #pragma unroll
    for (int i = 0; i < 6; i++) { local[i] = z[tid + i * 256]; s += local[i]; }
    s = warpSum(s);
    if (lane == 0) red[wid] = s;
    __syncthreads();
    float tot = 0.f;
    #pragma unroll
    for (int i = 0; i < 8; i++) tot += red[i];
    const float mu = tot * (1.f / 1536.f);
    __syncthreads();
    float v = 0.f;
    #pragma unroll
    for (int i = 0; i < 6; i++) { float d = local[i] - mu; v += d * d; }
    v = warpSum(v);
    if (lane == 0) red[wid] = v;
    __syncthreads();
    float tv = 0.f;
    #pragma unroll
    for (int i = 0; i < 8; i++) tv += red[i];
    const float rstd = rsqrtf(tv * (1.f / 1536.f) + 1e-6f);
    #pragma unroll
    for (int i = 0; i < 6; i++) {
        int c = tid + i * 256;
        z[c] = (local[i] - mu) * rstd * w[c] + bb[c];
    }
}

// ---------------- GLU with sequence flip: u = zf[n] * zb[N-1-n] --------------
__global__ __launch_bounds__(256) void glu_kernel(
    const float* __restrict__ Z, float* __restrict__ U)
{
    const long idx = (long)blockIdx.x * 256 + threadIdx.x;  // B*N*768
    const int c = (int)(idx % CDIM);
    const long bn = idx / CDIM;
    const int n = (int)(bn & 1023);
    const long b = bn >> 10;
    const float zf = Z[((b << 10) + n) * W2D + c];
    const float zb = Z[((b << 10) + (1023 - n)) * W2D + CDIM + c];
    U[idx] = zf * zb;
}

// ---------------- launch -----------------------------------------------------
extern "C" void kernel_launch(void* const* d_in, const int* in_sizes, int n_in,
                              void* d_out, int out_size)
{
    const float* x      = (const float*)d_in[0];
    const float* qkv_w  = (const float*)d_in[1];
    const float* proj_w = (const float*)d_in[2];
    const float* proj_b = (const float*)d_in[3];
    const float* W1     = (const float*)d_in[4];
    const float* b1     = (const float*)d_in[5];
    const float* ttt_w  = (const float*)d_in[6];
    const float* ttt_b  = (const float*)d_in[7];
    const float* pln_w  = (const float*)d_in[8];
    const float* pln_b  = (const float*)d_in[9];
    const float* lr_w   = (const float*)d_in[10];
    const float* lr_b   = (const float*)d_in[11];
    const float* tdelta = (const float*)d_in[12];
    float* out = (float*)d_out;

    float *p_qkv, *p_lr, *p_Z, *p_U;
    cudaGetSymbolAddress((void**)&p_qkv, g_qkv);
    cudaGetSymbolAddress((void**)&p_lr,  g_lr);
    cudaGetSymbolAddress((void**)&p_Z,   g_Z);
    cudaGetSymbolAddress((void**)&p_U,   g_U);

    cudaFuncSetAttribute(gemm_tf32_kernel,
                         cudaFuncAttributeMaxDynamicSharedMemorySize, SMEM_BYTES);

    const int M = BSZ * NSEQ;  // 16384

    // 1) qkv = x @ qkv_w                [16384,768] x [768,2304]
    gemm_tf32_kernel<<<dim3((3 * CDIM) / 128, M / 128), 256, SMEM_BYTES>>>(
        M, 3 * CDIM, CDIM, x, qkv_w, nullptr, p_qkv);
    // 2) lr gates
    lr_kernel<<<M / 8, 256>>>(x, lr_w, lr_b, p_lr);
    // 3) TTT scan -> Z [B,N,1536]
    ttt_kernel<<<dim3(NH2, BSZ), 512>>>(p_qkv, p_lr, W1, b1, ttt_w, ttt_b,
                                        tdelta, p_Z);
    // 4) post layernorm (in place)
    postln_kernel<<<M, 256>>>(p_Z, pln_w, pln_b);
    // 5) gated flip multiply -> U [B,N,768]
    glu_kernel<<<(M * CDIM) / 256, 256>>>(p_Z, p_U);
    // 6) out = U @ proj_w + proj_b     [16384,768] x [768,768]
    gemm_tf32_kernel<<<dim3(CDIM / 128, M / 128), 256, SMEM_BYTES>>>(
        M, CDIM, CDIM, p_U, proj_w, proj_b, out);
}

// round 16
// speedup vs baseline: 1.5570x; 1.3863x over previous
#include <cuda_runtime.h>
#include <cuda_bf16.h>
#include <stdint.h>
#include <math.h>

#define BSZ   16
#define NSEQ  1024
#define CDIM  768
#define NH2   24
#define HD    64
#define W2D   1536
#define KMB   16
#define NMB   64

// ---------------- scratch (static device globals; no allocation) -------------
__device__ float g_qkv[BSZ * NSEQ * 3 * CDIM];   // [B,N,2304]
__device__ float g_lr [BSZ * NSEQ * NH2];        // [B,N,24]
__device__ float g_Z  [BSZ * NSEQ * W2D];        // [B,N,1536]
__device__ float g_U  [BSZ * NSEQ * CDIM];       // [B,N,768]
__device__ __nv_bfloat16 g_ah[BSZ * NSEQ * CDIM];  // A hi (x or U)
__device__ __nv_bfloat16 g_al[BSZ * NSEQ * CDIM];  // A lo
__device__ __nv_bfloat16 g_bh[3 * CDIM * CDIM];    // B^T hi [N,K]
__device__ __nv_bfloat16 g_bl[3 * CDIM * CDIM];    // B^T lo

__device__ __forceinline__ float warpSum(float v) {
    #pragma unroll
    for (int o = 16; o; o >>= 1) v += __shfl_xor_sync(0xffffffffu, v, o);
    return v;
}

__device__ __forceinline__ void bf16_split(float v, __nv_bfloat16& hi,
                                           __nv_bfloat16& lo) {
    hi = __float2bfloat16_rn(v);
    lo = __float2bfloat16_rn(v - __bfloat162float(hi));
}

// ---------------- elementwise hi/lo split ------------------------------------
__global__ void split_kernel(const float* __restrict__ in,
                             __nv_bfloat16* __restrict__ oh,
                             __nv_bfloat16* __restrict__ ol, int n)
{
    int i = blockIdx.x * blockDim.x + threadIdx.x;
    if (i < n) {
        __nv_bfloat16 h, l;
        bf16_split(in[i], h, l);
        oh[i] = h; ol[i] = l;
    }
}

// ---------------- transpose + split: in[R][C] fp32 -> oh/ol[C][R] bf16 -------
__global__ __launch_bounds__(256) void tsplit_kernel(
    const float* __restrict__ in, __nv_bfloat16* __restrict__ oh,
    __nv_bfloat16* __restrict__ ol, int R, int C)
{
    __shared__ float t[32][33];
    const int tx = threadIdx.x & 31, ty = threadIdx.x >> 5;
    const int r0 = blockIdx.y * 32, c0 = blockIdx.x * 32;
    #pragma unroll
    for (int i = 0; i < 4; i++)
        t[ty + i * 8][tx] = in[(long)(r0 + ty + i * 8) * C + c0 + tx];
    __syncthreads();
    #pragma unroll
    for (int i = 0; i < 4; i++) {
        __nv_bfloat16 h, l;
        bf16_split(t[tx][ty + i * 8], h, l);
        const long o = (long)(c0 + ty + i * 8) * R + r0 + tx;
        oh[o] = h; ol[o] = l;
    }
}

// ================= bf16x3 tensor-core GEMM (mma.sync m16n8k16) ===============
// C[M,N] = A[M,K]@B[K,N] (+bias). A as bf16 hi/lo [M,K]; B as bf16 hi/lo
// B^T [N,K]. D += Al*Bh + Ah*Bl + Ah*Bh (fp32 accum). 256 thr, tile 128x128x32.
// Smem rows padded to 40 bf16 (80B) -> conflict-free 32-bit fragment LDS.

#define TILE_B   10240                  // 128 rows * 40 elems * 2B
#define STAGE_B  (4 * TILE_B)           // Ah,Al,Bh,Bl
#define GT_SMEM  (2 * STAGE_B)          // 81920

__device__ __forceinline__ void cp8(unsigned int sa, const __nv_bfloat16* g) {
    asm volatile("cp.async.ca.shared.global [%0], [%1], 8;" :: "r"(sa), "l"(g));
}
__device__ __forceinline__ void mma_bf16(float* d, const unsigned int* a,
                                         const unsigned int* b) {
    asm volatile(
        "mma.sync.aligned.m16n8k16.row.col.f32.bf16.bf16.f32 "
        "{%0,%1,%2,%3}, {%4,%5,%6,%7}, {%8,%9}, {%0,%1,%2,%3};\n"
        : "+f"(d[0]), "+f"(d[1]), "+f"(d[2]), "+f"(d[3])
        : "r"(a[0]), "r"(a[1]), "r"(a[2]), "r"(a[3]), "r"(b[0]), "r"(b[1]));
}

__device__ __forceinline__ void load_stage(
    unsigned int sst, const __nv_bfloat16* Ah, const __nv_bfloat16* Al,
    const __nv_bfloat16* Bh, const __nv_bfloat16* Bl,
    int Kd, int brow, int bcol, int k0, int tid)
{
    #pragma unroll
    for (int j = 0; j < 4; j++) {
        const int ch = tid + j * 256;              // 0..1023
        const int rr = ch >> 3;                    // tile row
        const int cc = ch & 7;                     // 8B chunk (4 bf16)
        const unsigned int so = (unsigned int)(rr * 80 + cc * 8);
        const long ga = (long)(brow + rr) * Kd + k0 + cc * 4;
        const long gb = (long)(bcol + rr) * Kd + k0 + cc * 4;
        cp8(sst + so,              Ah + ga);
        cp8(sst + TILE_B + so,     Al + ga);
        cp8(sst + 2 * TILE_B + so, Bh + gb);
        cp8(sst + 3 * TILE_B + so, Bl + gb);
    }
}

__global__ __launch_bounds__(256, 2) void gemm_bf16x3_kernel(
    int M, int N, int Kd,
    const __nv_bfloat16* __restrict__ Ah, const __nv_bfloat16* __restrict__ Al,
    const __nv_bfloat16* __restrict__ Bh, const __nv_bfloat16* __restrict__ Bl,
    const float* __restrict__ bias, float* __restrict__ C)
{
    extern __shared__ char smem[];
    const unsigned int sbase = (unsigned int)__cvta_generic_to_shared(smem);
    const int tid = threadIdx.x, wid = tid >> 5, lane = tid & 31;
    const int wr = wid >> 2, wc = wid & 3;       // warp grid 2x4 (64x32 tiles)
    const int g = lane >> 2, tg = lane & 3;
    const int brow = blockIdx.y * 128;
    const int bcol = blockIdx.x * 128;

    float acc[4][4][4];
    #pragma unroll
    for (int i = 0; i < 4; i++)
        #pragma unroll
        for (int j = 0; j < 4; j++)
            #pragma unroll
            for (int r = 0; r < 4; r++) acc[i][j][r] = 0.f;

    const int KT = Kd / 32;
    load_stage(sbase, Ah, Al, Bh, Bl, Kd, brow, bcol, 0, tid);
    asm volatile("cp.async.commit_group;");

    for (int kt = 0; kt < KT; kt++) {
        if (kt + 1 < KT) {
            load_stage(sbase + ((kt + 1) & 1) * STAGE_B, Ah, Al, Bh, Bl,
                       Kd, brow, bcol, (kt + 1) * 32, tid);
            asm volatile("cp.async.commit_group;");
            asm volatile("cp.async.wait_group 1;");
        } else {
            asm volatile("cp.async.wait_group 0;");
        }
        __syncthreads();

        const __nv_bfloat16* S = (const __nv_bfloat16*)(smem + (kt & 1) * STAGE_B);
        const __nv_bfloat16* SAh = S;
        const __nv_bfloat16* SAl = S + TILE_B / 2;
        const __nv_bfloat16* SBh = S + TILE_B;       // in bf16 elems
        const __nv_bfloat16* SBl = S + 3 * TILE_B / 2;

        #pragma unroll
        for (int ks = 0; ks < 2; ks++) {
            const int ko = ks * 16 + 2 * tg;         // k elem offset of pair
            // preload all B fragments (hi+lo): 4 j x 2 regs each
            unsigned int bhf[4][2], blf[4][2];
            #pragma unroll
            for (int j = 0; j < 4; j++) {
                const int row = wc * 32 + j * 8 + g;
                bhf[j][0] = *(const unsigned int*)&SBh[row * 40 + ko];
                bhf[j][1] = *(const unsigned int*)&SBh[row * 40 + ko + 8];
                blf[j][0] = *(const unsigned int*)&SBl[row * 40 + ko];
                blf[j][1] = *(const unsigned int*)&SBl[row * 40 + ko + 8];
            }
            #pragma unroll
            for (int i = 0; i < 4; i++) {
                const int row = wr * 64 + i * 16 + g;
                unsigned int ahf[4], alf[4];
                ahf[0] = *(const unsigned int*)&SAh[row * 40 + ko];
                ahf[1] = *(const unsigned int*)&SAh[(row + 8) * 40 + ko];
                ahf[2] = *(const unsigned int*)&SAh[row * 40 + ko + 8];
                ahf[3] = *(const unsigned int*)&SAh[(row + 8) * 40 + ko + 8];
                alf[0] = *(const unsigned int*)&SAl[row * 40 + ko];
                alf[1] = *(const unsigned int*)&SAl[(row + 8) * 40 + ko];
                alf[2] = *(const unsigned int*)&SAl[row * 40 + ko + 8];
                alf[3] = *(const unsigned int*)&SAl[(row + 8) * 40 + ko + 8];
                #pragma unroll
                for (int j = 0; j < 4; j++) {
                    mma_bf16(acc[i][j], alf, bhf[j]);
                    mma_bf16(acc[i][j], ahf, blf[j]);
                    mma_bf16(acc[i][j], ahf, bhf[j]);
                }
            }
        }
        __syncthreads();
    }

    #pragma unroll
    for (int i = 0; i < 4; i++) {
        #pragma unroll
        for (int j = 0; j < 4; j++) {
            const int row = brow + wr * 64 + i * 16 + g;
            const int col = bcol + wc * 32 + j * 8 + tg * 2;
            float2 v0 = make_float2(acc[i][j][0], acc[i][j][1]);
            float2 v1 = make_float2(acc[i][j][2], acc[i][j][3]);
            if (bias) {
                float2 bb = *(const float2*)(bias + col);
                v0.x += bb.x; v0.y += bb.y;
                v1.x += bb.x; v1.y += bb.y;
            }
            *(float2*)&C[(long)row * N + col] = v0;
            *(float2*)&C[(long)(row + 8) * N + col] = v1;
        }
    }
}

// ---------------- lr gate: warp-per-row, 8 rows per CTA ----------------------
__global__ __launch_bounds__(256) void lr_kernel(
    const float* __restrict__ x, const float* __restrict__ lr_w,
    const float* __restrict__ lr_b, float* __restrict__ lrout)
{
    const int w = threadIdx.x >> 5, lane = threadIdx.x & 31;
    const long bn = (long)blockIdx.x * 8 + w;
    const int b = (int)(bn >> 10), n = (int)(bn & 1023);
    const float* xf = x + bn * CDIM;
    const float* xb = x + ((long)(b << 10) + (1023 - n)) * CDIM;

    float acc[24];
    #pragma unroll
    for (int h = 0; h < 24; h++) acc[h] = 0.f;

    #pragma unroll 4
    for (int i = 0; i < 48; i++) {
        const int c = lane + i * 32;
        const float xv = (c < CDIM) ? xf[c] : xb[c - CDIM];
        const float4* wp = (const float4*)(lr_w + c * 24);
        #pragma unroll
        for (int q = 0; q < 6; q++) {
            float4 w4 = wp[q];
            acc[q * 4 + 0] += xv * w4.x;
            acc[q * 4 + 1] += xv * w4.y;
            acc[q * 4 + 2] += xv * w4.z;
            acc[q * 4 + 3] += xv * w4.w;
        }
    }
    float res = 0.f;
    #pragma unroll
    for (int h = 0; h < 24; h++) {
        float s = warpSum(acc[h]);
        if (lane == h) res = s;
    }
    if (lane < 24) {
        float v = 1.f / (1.f + expf(-(res + lr_b[lane])));
        lrout[bn * 24 + lane] = v * (1.f / 64.f);
    }
}

// ---------------- TTT scan: one (h,b) chain per CTA, 512 threads -------------
__global__ __launch_bounds__(512) void ttt_kernel(
    const float* __restrict__ qkv, const float* __restrict__ lrbuf,
    const float* __restrict__ W1,  const float* __restrict__ b1,
    const float* __restrict__ lnw, const float* __restrict__ lnb,
    const float* __restrict__ tdelta, float* __restrict__ Zout)
{
    const int h = blockIdx.x;
    const int b = blockIdx.y;
    __shared__ float Ws[HD][HD];
    __shared__ float xq_s[KMB][HD], xk_s[KMB][HD], grad_s[KMB][HD];
    __shared__ float lrm_s[KMB];
    const int tid = threadIdx.x, wi = tid >> 5, lane = tid & 31;

    for (int i = tid; i < HD * HD; i += 512)
        Ws[i >> 6][i & 63] = W1[h * HD * HD + i];

    const int d0 = 2 * lane, d1 = 2 * lane + 1;
    float breg0 = b1[h * HD + d0], breg1 = b1[h * HD + d1];
    const float g0  = lnw[h * HD + d0], g1  = lnw[h * HD + d1];
    const float bt0 = lnb[h * HD + d0], bt1 = lnb[h * HD + d1];
    const float tok_i    = fmaxf(1.f / (float)(wi + 1) + tdelta[wi], 0.f);
    const float tok_last = fmaxf(1.f / 16.f + tdelta[15], 0.f);
    const float inv = powf(10000.f, -(float)lane / 32.f);
    float sv, cv;
    sincosf((float)wi * inv, &sv, &cv);
    const bool  flipd   = (h >= 12);
    const int   srcCol  = (flipd ? (h - 12) : h) * HD;

    for (int m = 0; m < NMB; m++) {
        const int n  = m * KMB + wi;
        const int sn = flipd ? (NSEQ - 1 - n) : n;
        const float* base = qkv + (long)(b * NSEQ + sn) * (3 * CDIM) + srcCol;
        float q0 = base[d0],            q1 = base[d1];
        float k0 = base[CDIM + d0],     k1 = base[CDIM + d1];
        float v0 = base[2 * CDIM + d0], v1 = base[2 * CDIM + d1];
        const float qr0 = q0 * cv - q1 * sv, qr1 = q0 * sv + q1 * cv;
        const float kr0 = k0 * cv - k1 * sv, kr1 = k0 * sv + k1 * cv;
        xq_s[wi][d0] = qr0; xq_s[wi][d1] = qr1;
        xk_s[wi][d0] = kr0; xk_s[wi][d1] = kr1;
        if (wi == 0 && lane < KMB)
            lrm_s[lane] = lrbuf[(long)(b * NSEQ + m * KMB + lane) * NH2 + h];
        __syncthreads();

        float z0 = breg0, z1 = breg1, a0 = 0.f, a1 = 0.f;
        #pragma unroll 16
        for (int e = 0; e < HD; e++) {
            const float ke = xk_s[wi][e], qe = xq_s[wi][e];
            const float2 wv = *(const float2*)&Ws[e][d0];
            z0 += ke * wv.x; z1 += ke * wv.y;
            a0 += qe * wv.x; a1 += qe * wv.y;
        }
        const float mu = warpSum(z0 + z1) * (1.f / 64.f);
        const float zc0 = z0 - mu, zc1 = z1 - mu;
        const float var = warpSum(zc0 * zc0 + zc1 * zc1) * (1.f / 64.f);
        const float rstd = rsqrtf(var + 1e-6f);
        const float xh0 = zc0 * rstd, xh1 = zc1 * rstd;
        const float t0 = v0 - kr0, t1 = v1 - kr1;
        const float go0 = g0 * xh0 + bt0 - t0, go1 = g1 * xh1 + bt1 - t1;
        const float gx0 = go0 * g0, gx1 = go1 * g1;
        const float s1 = warpSum(gx0 + gx1);
        const float s2 = warpSum(gx0 * xh0 + gx1 * xh1);
        const float cdn = rstd * (1.f / 64.f);
        const float gr0 = (64.f * gx0 - s1 - xh0 * s2) * cdn;
        const float gr1 = (64.f * gx1 - s1 - xh1 * s2) * cdn;
        grad_s[wi][d0] = gr0; grad_s[wi][d1] = gr1;
        __syncthreads();

        float acc0 = a0 + breg0, acc1 = a1 + breg1;
        for (int j = 0; j <= wi; j++) {
            const float2 kk2 = *(const float2*)&xk_s[j][d0];
            float p = warpSum(qr0 * kk2.x + qr1 * kk2.y);
            const float coef = tok_i * lrm_s[j] * (1.f + p);
            const float2 gg2 = *(const float2*)&grad_s[j][d0];
            acc0 -= coef * gg2.x;
            acc1 -= coef * gg2.y;
        }
        const float mu2 = warpSum(acc0 + acc1) * (1.f / 64.f);
        const float c0 = acc0 - mu2, c1 = acc1 - mu2;
        const float var2 = warpSum(c0 * c0 + c1 * c1) * (1.f / 64.f);
        const float rs2 = rsqrtf(var2 + 1e-6f);
        float2 ov = make_float2(qr0 + g0 * c0 * rs2 + bt0,
                                qr1 + g1 * c1 * rs2 + bt1);
        *(float2*)&Zout[(long)(b * NSEQ + n) * W2D + h * HD + d0] = ov;

        float db0 = 0.f, db1 = 0.f;
        #pragma unroll
        for (int k = 0; k < KMB; k++) {
            const float c = lrm_s[k];
            const float2 gg2 = *(const float2*)&grad_s[k][d0];
            db0 += c * gg2.x; db1 += c * gg2.y;
        }
        breg0 -= tok_last * db0;
        breg1 -= tok_last * db1;

        {
            const int e  = tid >> 3;
            const int dd = (tid & 7) * 8;
            float wacc[8];
            #pragma unroll
            for (int d = 0; d < 8; d++) wacc[d] = Ws[e][dd + d];
            #pragma unroll
            for (int k = 0; k < KMB; k++) {
                const float c = tok_last * lrm_s[k] * xk_s[k][e];
                const float4 ga = *(const float4*)&grad_s[k][dd];
                const float4 gb = *(const float4*)&grad_s[k][dd + 4];
                wacc[0] -= c * ga.x; wacc[1] -= c * ga.y;
                wacc[2] -= c * ga.z; wacc[3] -= c * ga.w;
                wacc[4] -= c * gb.x; wacc[5] -= c * gb.y;
                wacc[6] -= c * gb.z; wacc[7] -= c * gb.w;
            }
            #pragma unroll
            for (int d = 0; d < 8; d++) Ws[e][dd + d] = wacc[d];
        }
        __syncthreads();
    }
}

// ---------------- post layernorm over W2=1536, in place ----------------------
__global__ __launch_bounds__(256) void postln_kernel(
    float* __restrict__ Z, const float* __restrict__ w, const float* __restrict__ bb)
{
    float* z = Z + (long)blockIdx.x * W2D;
    __shared__ float red[8];
    const int tid = threadIdx.x, lane = tid & 31, wid = tid >> 5;
    float local[6];
    float s = 0.f;
    #pragma unroll
    for (int i = 0; i < 6; i++) { local[i] = z[tid + i * 256]; s += local[i]; }
    s = warpSum(s);
    if (lane == 0) red[wid] = s;
    __syncthreads();
    float tot = 0.f;
    #pragma unroll
    for (int i = 0; i < 8; i++) tot += red[i];
    const float mu = tot * (1.f / 1536.f);
    __syncthreads();
    float v = 0.f;
    #pragma unroll
    for (int i = 0; i < 6; i++) { float d = local[i] - mu; v += d * d; }
    v = warpSum(v);
    if (lane == 0) red[wid] = v;
    __syncthreads();
    float tv = 0.f;
    #pragma unroll
    for (int i = 0; i < 8; i++) tv += red[i];
    const float rstd = rsqrtf(tv * (1.f / 1536.f) + 1e-6f);
    #pragma unroll
    for (int i = 0; i < 6; i++) {
        int c = tid + i * 256;
        z[c] = (local[i] - mu) * rstd * w[c] + bb[c];
    }
}

// ---------------- GLU with sequence flip: u = zf[n] * zb[N-1-n] --------------
__global__ __launch_bounds__(256) void glu_kernel(
    const float* __restrict__ Z, float* __restrict__ U)
{
    const long idx = (long)blockIdx.x * 256 + threadIdx.x;
    const int c = (int)(idx % CDIM);
    const long bn = idx / CDIM;
    const int n = (int)(bn & 1023);
    const long b = bn >> 10;
    const float zf = Z[((b << 10) + n) * W2D + c];
    const float zb = Z[((b << 10) + (1023 - n)) * W2D + CDIM + c];
    U[idx] = zf * zb;
}

// ---------------- launch -----------------------------------------------------
extern "C" void kernel_launch(void* const* d_in, const int* in_sizes, int n_in,
                              void* d_out, int out_size)
{
    const float* x      = (const float*)d_in[0];
    const float* qkv_w  = (const float*)d_in[1];
    const float* proj_w = (const float*)d_in[2];
    const float* proj_b = (const float*)d_in[3];
    const float* W1     = (const float*)d_in[4];
    const float* b1     = (const float*)d_in[5];
    const float* ttt_w  = (const float*)d_in[6];
    const float* ttt_b  = (const float*)d_in[7];
    const float* pln_w  = (const float*)d_in[8];
    const float* pln_b  = (const float*)d_in[9];
    const float* lr_w   = (const float*)d_in[10];
    const float* lr_b   = (const float*)d_in[11];
    const float* tdelta = (const float*)d_in[12];
    float* out = (float*)d_out;

    float *p_qkv, *p_lr, *p_Z, *p_U;
    __nv_bfloat16 *p_ah, *p_al, *p_bh, *p_bl;
    cudaGetSymbolAddress((void**)&p_qkv, g_qkv);
    cudaGetSymbolAddress((void**)&p_lr,  g_lr);
    cudaGetSymbolAddress((void**)&p_Z,   g_Z);
    cudaGetSymbolAddress((void**)&p_U,   g_U);
    cudaGetSymbolAddress((void**)&p_ah,  g_ah);
    cudaGetSymbolAddress((void**)&p_al,  g_al);
    cudaGetSymbolAddress((void**)&p_bh,  g_bh);
    cudaGetSymbolAddress((void**)&p_bl,  g_bl);

    cudaFuncSetAttribute(gemm_bf16x3_kernel,
                         cudaFuncAttributeMaxDynamicSharedMemorySize, GT_SMEM);

    const int M = BSZ * NSEQ;            // 16384
    const int NE = M * CDIM;

    // 1) split x -> bf16 hi/lo;  transpose+split qkv_w -> B^T hi/lo
    split_kernel<<<(NE + 511) / 512, 512>>>(x, p_ah, p_al, NE);
    tsplit_kernel<<<dim3((3 * CDIM) / 32, CDIM / 32), 256>>>(
        qkv_w, p_bh, p_bl, CDIM, 3 * CDIM);
    // 2) qkv = x @ qkv_w  (bf16x3 tensor cores)
    gemm_bf16x3_kernel<<<dim3((3 * CDIM) / 128, M / 128), 256, GT_SMEM>>>(
        M, 3 * CDIM, CDIM, p_ah, p_al, p_bh, p_bl, nullptr, p_qkv);
    // 3) lr gates
    lr_kernel<<<M / 8, 256>>>(x, lr_w, lr_b, p_lr);
    // 4) TTT scan -> Z
    ttt_kernel<<<dim3(NH2, BSZ), 512>>>(p_qkv, p_lr, W1, b1, ttt_w, ttt_b,
                                        tdelta, p_Z);
    // 5) post layernorm (in place)
    postln_kernel<<<M, 256>>>(p_Z, pln_w, pln_b);
    // 6) gated flip multiply -> U
    glu_kernel<<<(M * CDIM) / 256, 256>>>(p_Z, p_U);
    // 7) split U;  transpose+split proj_w
    split_kernel<<<(NE + 511) / 512, 512>>>(p_U, p_ah, p_al, NE);
    tsplit_kernel<<<dim3(CDIM / 32, CDIM / 32), 256>>>(
        proj_w, p_bh, p_bl, CDIM, CDIM);
    // 8) out = U @ proj_w + proj_b
    gemm_bf16x3_kernel<<<dim3(CDIM / 128, M / 128), 256, GT_SMEM>>>(
        M, CDIM, CDIM, p_ah, p_al, p_bh, p_bl, proj_b, out);
}